// round 11
// baseline (speedup 1.0000x reference)
#include <cuda_runtime.h>
#include <math.h>

#define NQ 14
#define BATCH 2048
#define ELEMS 64               // batch elements per block
#define BLK (ELEMS * NQ)       // 896: one thread per (element, qubit)
#define ROW 15                 // smem row stride (odd -> conflict-free)

struct Masks {
    unsigned S[NQ];
    unsigned T[NQ];
    int      k4[NQ];
};

__host__ __device__ constexpr Masks compute_masks() {
    Masks ms{};
    unsigned M[NQ] = {};
    for (int u = 0; u < NQ; ++u) {
        unsigned j = 1u << (13 - u);
        for (int step = 2; step >= 1; --step)
            for (int c = NQ - 1; c >= 0; --c) {
                int t = (c + step) % NQ;
                if ((j >> (13 - c)) & 1u) j ^= 1u << (13 - t);
            }
        for (int w = 0; w < NQ; ++w)
            if ((j >> (13 - w)) & 1u) M[w] |= 1u << u;
    }
    for (int w = 0; w < NQ; ++w) {
        unsigned t = 0;
        for (int r = 0; r < NQ; ++r)
            if ((M[r] >> w) & 1u) t |= 1u << r;
        ms.T[w] = t;
    }
    unsigned A[NQ] = {};
    unsigned I[NQ] = {};
    for (int r = 0; r < NQ; ++r) { A[r] = M[r]; I[r] = 1u << r; }
    for (int col = 0; col < NQ; ++col) {
        int piv = col;
        while (((A[piv] >> col) & 1u) == 0u) ++piv;
        unsigned ta = A[col]; A[col] = A[piv]; A[piv] = ta;
        unsigned ti = I[col]; I[col] = I[piv]; I[piv] = ti;
        for (int r = 0; r < NQ; ++r)
            if (r != col && ((A[r] >> col) & 1u)) { A[r] ^= A[col]; I[r] ^= I[col]; }
    }
    for (int w = 0; w < NQ; ++w) ms.S[w] = I[w];
    for (int w = 0; w < NQ; ++w) {
        unsigned xm = ms.S[w] & ms.T[w];
        int cnt = 0;
        for (int b = 0; b < NQ; ++b) cnt += (int)((xm >> b) & 1u);
        ms.k4[w] = cnt & 3;
    }
    return ms;
}

__host__ __device__ constexpr unsigned pack_k4() {
    Masks ms = compute_masks();
    unsigned p = 0;
    for (int w = 0; w < NQ; ++w) p |= ((unsigned)ms.k4[w]) << (2 * w);
    return p;
}

// ---- constexpr bit helpers ----
__host__ __device__ constexpr int cpop(unsigned m) {
    int c = 0;
    while (m) { c += (int)(m & 1u); m >>= 1; }
    return c;
}
__host__ __device__ constexpr int cctz(unsigned m) {
    int c = 0;
    while (((m >> c) & 1u) == 0u) ++c;
    return c;
}
__host__ __device__ constexpr unsigned clow(unsigned m, int n) {
    unsigned r = 0;
    int c = 0;
    for (int b = 0; b < 32 && c < n; ++b)
        if ((m >> b) & 1u) { r |= 1u << b; ++c; }
    return r;
}

// Balanced-tree product over the set bits of MASK.
template<unsigned MASK>
__device__ __forceinline__ float prodm(const float* __restrict__ v) {
    if constexpr (MASK == 0u) {
        return 1.0f;
    } else if constexpr ((MASK & (MASK - 1u)) == 0u) {
        return v[cctz(MASK)];
    } else {
        constexpr unsigned lo = clow(MASK, cpop(MASK) / 2);
        return prodm<lo>(v) * prodm<MASK & ~lo>(v);
    }
}

template<int W>
__device__ __forceinline__ float emitW(const float* __restrict__ z,
                                       const float* __restrict__ G,
                                       const float* __restrict__ y,
                                       float c1, float c2, float c3) {
    constexpr unsigned S = compute_masks().S[W];
    constexpr unsigned T = compute_masks().T[W];
    float Zp = prodm<S>(z);
    float R1 = prodm<T>(G);
    float R2 = prodm<S & T>(y) * prodm<S & ~T>(z) * prodm<T & ~S>(G);
    return c1 * Zp - c2 * R1 - c3 * R2;
}

__global__ void __launch_bounds__(BLK)
qulinear_kernel(const float* __restrict__ x, const float* __restrict__ u3,
                float* __restrict__ out) {
    __shared__ float zs[ELEMS * ROW], Gs[ELEMS * ROW], ys[ELEMS * ROW];

    const int tid = threadIdx.x;
    const int b0  = blockIdx.x * ELEMS;

    // Phase-2 identity: warp-uniform output qubit
    const int warp = tid >> 5;                 // 0..27
    const int w    = warp % NQ;                // output qubit (uniform per warp)
    const int e    = (tid & 31) + 32 * (warp / NQ);  // element 0..63

    // ---- Issue global loads up front (overlap) ----
    const float xv  = x[b0 * NQ + tid];        // 896 contiguous floats
    const float th  = __ldg(&u3[w * 3 + 0]);
    const float lam = __ldg(&u3[w * 3 + 2]);   // phi cancels in U3^dag Z U3

    // ---- U3 coefficients via MUFU intrinsics (args in [0,2pi], err ~2^-21;
    //      budget 1e-3, measured 5.8e-7) ----
    const float st = __sinf(th);
    const float ct = __cosf(th);
    const float sl = __sinf(lam);
    const float cl = __cosf(lam);
    constexpr unsigned K4P = pack_k4();
    const int k = (int)((K4P >> (2 * w)) & 3u);
    const float f = (k == 0) ? cl : (k == 1) ? -sl : (k == 2) ? -cl : sl;
    const float c1 = ct;
    const float c2 = st * cl;
    const float c3 = st * f;

    // ---- Phase 1: per-(element,qubit) scalars into padded smem ----
    {
        const int e1 = tid / NQ;
        const int u1 = tid - e1 * NQ;
        const int si = e1 * ROW + u1;
        float x2 = xv * xv;
        float i1 = rsqrtf(fmaf(xv, xv, 1.0f)); // 1/sqrt(1+x^2)
        float i2 = rsqrtf(fmaf(x2, x2, 1.0f)); // 1/sqrt(1+x^4)
        float gi = i1 * i2;
        zs[si] = -xv * i1;
        Gs[si] = gi;
        ys[si] = x2 * gi;
    }
    __syncthreads();

    // ---- Phase 2: warp-uniform w, tree-structured products ----
    {
        const float* z = zs + e * ROW;
        const float* G = Gs + e * ROW;
        const float* y = ys + e * ROW;
        float r;
        switch (w) {
            case 0:  r = emitW<0>(z, G, y, c1, c2, c3);  break;
            case 1:  r = emitW<1>(z, G, y, c1, c2, c3);  break;
            case 2:  r = emitW<2>(z, G, y, c1, c2, c3);  break;
            case 3:  r = emitW<3>(z, G, y, c1, c2, c3);  break;
            case 4:  r = emitW<4>(z, G, y, c1, c2, c3);  break;
            case 5:  r = emitW<5>(z, G, y, c1, c2, c3);  break;
            case 6:  r = emitW<6>(z, G, y, c1, c2, c3);  break;
            case 7:  r = emitW<7>(z, G, y, c1, c2, c3);  break;
            case 8:  r = emitW<8>(z, G, y, c1, c2, c3);  break;
            case 9:  r = emitW<9>(z, G, y, c1, c2, c3);  break;
            case 10: r = emitW<10>(z, G, y, c1, c2, c3); break;
            case 11: r = emitW<11>(z, G, y, c1, c2, c3); break;
            case 12: r = emitW<12>(z, G, y, c1, c2, c3); break;
            default: r = emitW<13>(z, G, y, c1, c2, c3); break;
        }
        out[(b0 + e) * NQ + w] = r;
    }
}

extern "C" void kernel_launch(void* const* d_in, const int* in_sizes, int n_in,
                              void* d_out, int out_size) {
    const float* x  = (const float*)d_in[0];
    const float* u3 = (const float*)d_in[1];
    if (n_in >= 2 && in_sizes[0] == NQ * 3 && in_sizes[1] == BATCH * NQ) {
        const float* t = x; x = u3; u3 = t;
    }
    float* out = (float*)d_out;
    qulinear_kernel<<<BATCH / ELEMS, BLK>>>(x, u3, out);
}

// round 12
// speedup vs baseline: 1.0677x; 1.0677x over previous
#include <cuda_runtime.h>
#include <math.h>

#define NQ 14
#define BATCH 2048
#define ELEMS 32               // batch elements per block (best measured config)
#define BLK (ELEMS * NQ)       // 448: one thread per (element, qubit)
#define ROW 15                 // smem row stride (odd -> conflict-free)

struct Masks {
    unsigned S[NQ];
    unsigned T[NQ];
    int      k4[NQ];
};

__host__ __device__ constexpr Masks compute_masks() {
    Masks ms{};
    unsigned M[NQ] = {};
    for (int u = 0; u < NQ; ++u) {
        unsigned j = 1u << (13 - u);
        for (int step = 2; step >= 1; --step)
            for (int c = NQ - 1; c >= 0; --c) {
                int t = (c + step) % NQ;
                if ((j >> (13 - c)) & 1u) j ^= 1u << (13 - t);
            }
        for (int w = 0; w < NQ; ++w)
            if ((j >> (13 - w)) & 1u) M[w] |= 1u << u;
    }
    for (int w = 0; w < NQ; ++w) {
        unsigned t = 0;
        for (int r = 0; r < NQ; ++r)
            if ((M[r] >> w) & 1u) t |= 1u << r;
        ms.T[w] = t;
    }
    unsigned A[NQ] = {};
    unsigned I[NQ] = {};
    for (int r = 0; r < NQ; ++r) { A[r] = M[r]; I[r] = 1u << r; }
    for (int col = 0; col < NQ; ++col) {
        int piv = col;
        while (((A[piv] >> col) & 1u) == 0u) ++piv;
        unsigned ta = A[col]; A[col] = A[piv]; A[piv] = ta;
        unsigned ti = I[col]; I[col] = I[piv]; I[piv] = ti;
        for (int r = 0; r < NQ; ++r)
            if (r != col && ((A[r] >> col) & 1u)) { A[r] ^= A[col]; I[r] ^= I[col]; }
    }
    for (int w = 0; w < NQ; ++w) ms.S[w] = I[w];
    for (int w = 0; w < NQ; ++w) {
        unsigned xm = ms.S[w] & ms.T[w];
        int cnt = 0;
        for (int b = 0; b < NQ; ++b) cnt += (int)((xm >> b) & 1u);
        ms.k4[w] = cnt & 3;
    }
    return ms;
}

__host__ __device__ constexpr unsigned pack_k4() {
    Masks ms = compute_masks();
    unsigned p = 0;
    for (int w = 0; w < NQ; ++w) p |= ((unsigned)ms.k4[w]) << (2 * w);
    return p;
}

// ---- constexpr bit helpers ----
__host__ __device__ constexpr int cpop(unsigned m) {
    int c = 0;
    while (m) { c += (int)(m & 1u); m >>= 1; }
    return c;
}
__host__ __device__ constexpr int cctz(unsigned m) {
    int c = 0;
    while (((m >> c) & 1u) == 0u) ++c;
    return c;
}
__host__ __device__ constexpr unsigned clow(unsigned m, int n) {
    unsigned r = 0;
    int c = 0;
    for (int b = 0; b < 32 && c < n; ++b)
        if ((m >> b) & 1u) { r |= 1u << b; ++c; }
    return r;
}

// Balanced-tree product over the set bits of MASK.
template<unsigned MASK>
__device__ __forceinline__ float prodm(const float* __restrict__ v) {
    if constexpr (MASK == 0u) {
        return 1.0f;
    } else if constexpr ((MASK & (MASK - 1u)) == 0u) {
        return v[cctz(MASK)];
    } else {
        constexpr unsigned lo = clow(MASK, cpop(MASK) / 2);
        return prodm<lo>(v) * prodm<MASK & ~lo>(v);
    }
}

template<int W>
__device__ __forceinline__ float emitW(const float* __restrict__ z,
                                       const float* __restrict__ G,
                                       const float* __restrict__ y,
                                       float c1, float c2, float c3) {
    constexpr unsigned S = compute_masks().S[W];
    constexpr unsigned T = compute_masks().T[W];
    float Zp = prodm<S>(z);
    float R1 = prodm<T>(G);
    float R2 = prodm<S & T>(y) * prodm<S & ~T>(z) * prodm<T & ~S>(G);
    return c1 * Zp - c2 * R1 - c3 * R2;
}

__global__ void __launch_bounds__(BLK)
qulinear_kernel(const float* __restrict__ x, const float* __restrict__ u3,
                float* __restrict__ out) {
    __shared__ float zs[ELEMS * ROW], Gs[ELEMS * ROW], ys[ELEMS * ROW];

    const int tid = threadIdx.x;
    const int b0  = blockIdx.x * ELEMS;

    const int w = tid >> 5;                    // output qubit: uniform per warp
    const int e = tid & 31;                    // element = lane

    // ---- Issue global loads up front (overlap) ----
    const float xv  = x[b0 * NQ + tid];        // 448 contiguous floats
    const float th  = __ldg(&u3[w * 3 + 0]);
    const float lam = __ldg(&u3[w * 3 + 2]);   // phi cancels in U3^dag Z U3

    // ---- U3 coefficients via MUFU intrinsics (args in [0,2pi], err ~2^-21;
    //      budget 1e-3, measured 5.8e-7) ----
    const float st = __sinf(th);
    const float ct = __cosf(th);
    const float sl = __sinf(lam);
    const float cl = __cosf(lam);
    constexpr unsigned K4P = pack_k4();
    const int k = (int)((K4P >> (2 * w)) & 3u);
    const float f = (k == 0) ? cl : (k == 1) ? -sl : (k == 2) ? -cl : sl;
    const float c1 = ct;
    const float c2 = st * cl;
    const float c3 = st * f;

    // ---- Phase 1: per-(element,qubit) scalars into padded smem ----
    {
        const int e1 = tid / NQ;
        const int u1 = tid - e1 * NQ;
        const int si = e1 * ROW + u1;
        float x2 = xv * xv;
        float i1 = rsqrtf(fmaf(xv, xv, 1.0f)); // 1/sqrt(1+x^2)
        float i2 = rsqrtf(fmaf(x2, x2, 1.0f)); // 1/sqrt(1+x^4)
        float gi = i1 * i2;
        zs[si] = -xv * i1;
        Gs[si] = gi;
        ys[si] = x2 * gi;
    }
    __syncthreads();

    // ---- Phase 2: warp-uniform w, tree-structured products ----
    float r;
    {
        const float* z = zs + e * ROW;
        const float* G = Gs + e * ROW;
        const float* y = ys + e * ROW;
        switch (w) {
            case 0:  r = emitW<0>(z, G, y, c1, c2, c3);  break;
            case 1:  r = emitW<1>(z, G, y, c1, c2, c3);  break;
            case 2:  r = emitW<2>(z, G, y, c1, c2, c3);  break;
            case 3:  r = emitW<3>(z, G, y, c1, c2, c3);  break;
            case 4:  r = emitW<4>(z, G, y, c1, c2, c3);  break;
            case 5:  r = emitW<5>(z, G, y, c1, c2, c3);  break;
            case 6:  r = emitW<6>(z, G, y, c1, c2, c3);  break;
            case 7:  r = emitW<7>(z, G, y, c1, c2, c3);  break;
            case 8:  r = emitW<8>(z, G, y, c1, c2, c3);  break;
            case 9:  r = emitW<9>(z, G, y, c1, c2, c3);  break;
            case 10: r = emitW<10>(z, G, y, c1, c2, c3); break;
            case 11: r = emitW<11>(z, G, y, c1, c2, c3); break;
            case 12: r = emitW<12>(z, G, y, c1, c2, c3); break;
            default: r = emitW<13>(z, G, y, c1, c2, c3); break;
        }
    }

    // ---- Phase 3: transpose through smem (reuse zs) for coalesced stores ----
    __syncthreads();                           // zs reads above are complete
    zs[e * ROW + w] = r;                       // [element][qubit], padded
    __syncthreads();
    {
        const int e1 = tid / NQ;
        const int u1 = tid - e1 * NQ;
        out[b0 * NQ + tid] = zs[e1 * ROW + u1];  // 448 contiguous floats
    }
}

extern "C" void kernel_launch(void* const* d_in, const int* in_sizes, int n_in,
                              void* d_out, int out_size) {
    const float* x  = (const float*)d_in[0];
    const float* u3 = (const float*)d_in[1];
    if (n_in >= 2 && in_sizes[0] == NQ * 3 && in_sizes[1] == BATCH * NQ) {
        const float* t = x; x = u3; u3 = t;
    }
    float* out = (float*)d_out;
    qulinear_kernel<<<BATCH / ELEMS, BLK>>>(x, u3, out);
}

// round 13
// speedup vs baseline: 1.2577x; 1.1779x over previous
#include <cuda_runtime.h>
#include <math.h>

#define NQ 14
#define BATCH 2048
#define ELEMS 32               // batch elements per block (best measured config)
#define BLK (ELEMS * NQ)       // 448: one thread per (element, qubit)
#define ROW 15                 // smem row stride (odd -> conflict-free)

struct Masks {
    unsigned S[NQ];
    unsigned T[NQ];
    int      k4[NQ];
};

__host__ __device__ constexpr Masks compute_masks() {
    Masks ms{};
    unsigned M[NQ] = {};
    for (int u = 0; u < NQ; ++u) {
        unsigned j = 1u << (13 - u);
        for (int step = 2; step >= 1; --step)
            for (int c = NQ - 1; c >= 0; --c) {
                int t = (c + step) % NQ;
                if ((j >> (13 - c)) & 1u) j ^= 1u << (13 - t);
            }
        for (int w = 0; w < NQ; ++w)
            if ((j >> (13 - w)) & 1u) M[w] |= 1u << u;
    }
    for (int w = 0; w < NQ; ++w) {
        unsigned t = 0;
        for (int r = 0; r < NQ; ++r)
            if ((M[r] >> w) & 1u) t |= 1u << r;
        ms.T[w] = t;
    }
    unsigned A[NQ] = {};
    unsigned I[NQ] = {};
    for (int r = 0; r < NQ; ++r) { A[r] = M[r]; I[r] = 1u << r; }
    for (int col = 0; col < NQ; ++col) {
        int piv = col;
        while (((A[piv] >> col) & 1u) == 0u) ++piv;
        unsigned ta = A[col]; A[col] = A[piv]; A[piv] = ta;
        unsigned ti = I[col]; I[col] = I[piv]; I[piv] = ti;
        for (int r = 0; r < NQ; ++r)
            if (r != col && ((A[r] >> col) & 1u)) { A[r] ^= A[col]; I[r] ^= I[col]; }
    }
    for (int w = 0; w < NQ; ++w) ms.S[w] = I[w];
    for (int w = 0; w < NQ; ++w) {
        unsigned xm = ms.S[w] & ms.T[w];
        int cnt = 0;
        for (int b = 0; b < NQ; ++b) cnt += (int)((xm >> b) & 1u);
        ms.k4[w] = cnt & 3;
    }
    return ms;
}

__host__ __device__ constexpr unsigned pack_k4() {
    Masks ms = compute_masks();
    unsigned p = 0;
    for (int w = 0; w < NQ; ++w) p |= ((unsigned)ms.k4[w]) << (2 * w);
    return p;
}

// ---- constexpr bit helpers ----
__host__ __device__ constexpr int cpop(unsigned m) {
    int c = 0;
    while (m) { c += (int)(m & 1u); m >>= 1; }
    return c;
}
__host__ __device__ constexpr int cctz(unsigned m) {
    int c = 0;
    while (((m >> c) & 1u) == 0u) ++c;
    return c;
}
__host__ __device__ constexpr unsigned clow(unsigned m, int n) {
    unsigned r = 0;
    int c = 0;
    for (int b = 0; b < 32 && c < n; ++b)
        if ((m >> b) & 1u) { r |= 1u << b; ++c; }
    return r;
}

// Balanced-tree product over the set bits of MASK.
template<unsigned MASK>
__device__ __forceinline__ float prodm(const float* __restrict__ v) {
    if constexpr (MASK == 0u) {
        return 1.0f;
    } else if constexpr ((MASK & (MASK - 1u)) == 0u) {
        return v[cctz(MASK)];
    } else {
        constexpr unsigned lo = clow(MASK, cpop(MASK) / 2);
        return prodm<lo>(v) * prodm<MASK & ~lo>(v);
    }
}

template<int W>
__device__ __forceinline__ float emitW(const float* __restrict__ z,
                                       const float* __restrict__ G,
                                       const float* __restrict__ y,
                                       float c1, float c2, float c3) {
    constexpr unsigned S = compute_masks().S[W];
    constexpr unsigned T = compute_masks().T[W];
    float Zp = prodm<S>(z);
    float R1 = prodm<T>(G);
    float R2 = prodm<S & T>(y) * prodm<S & ~T>(z) * prodm<T & ~S>(G);
    return c1 * Zp - c2 * R1 - c3 * R2;
}

__global__ void __launch_bounds__(BLK)
qulinear_kernel(const float* __restrict__ x, const float* __restrict__ u3,
                float* __restrict__ out) {
    __shared__ float zs[ELEMS * ROW], Gs[ELEMS * ROW], ys[ELEMS * ROW];
    __shared__ float rs[ELEMS * ROW];          // dedicated result buffer

    const int tid = threadIdx.x;
    const int b0  = blockIdx.x * ELEMS;

    const int w = tid >> 5;                    // output qubit: uniform per warp
    const int e = tid & 31;                    // element = lane

    // ---- Issue global loads up front (overlap) ----
    const float xv  = x[b0 * NQ + tid];        // 448 contiguous floats
    const float th  = __ldg(&u3[w * 3 + 0]);
    const float lam = __ldg(&u3[w * 3 + 2]);   // phi cancels in U3^dag Z U3

    // ---- U3 coefficients via MUFU intrinsics (args in [0,2pi], err ~2^-21;
    //      budget 1e-3, measured 5.8e-7) ----
    const float st = __sinf(th);
    const float ct = __cosf(th);
    const float sl = __sinf(lam);
    const float cl = __cosf(lam);
    constexpr unsigned K4P = pack_k4();
    const int k = (int)((K4P >> (2 * w)) & 3u);
    const float f = (k == 0) ? cl : (k == 1) ? -sl : (k == 2) ? -cl : sl;
    const float c1 = ct;
    const float c2 = st * cl;
    const float c3 = st * f;

    // ---- Phase 1: per-(element,qubit) scalars into padded smem ----
    {
        const int e1 = tid / NQ;
        const int u1 = tid - e1 * NQ;
        const int si = e1 * ROW + u1;
        float x2 = xv * xv;
        float i1 = rsqrtf(fmaf(xv, xv, 1.0f)); // 1/sqrt(1+x^2)
        float i2 = rsqrtf(fmaf(x2, x2, 1.0f)); // 1/sqrt(1+x^4)
        float gi = i1 * i2;
        zs[si] = -xv * i1;
        Gs[si] = gi;
        ys[si] = x2 * gi;
    }
    __syncthreads();

    // ---- Phase 2: warp-uniform w, tree products; write result straight to
    //      the dedicated buffer (no hazard, no extra barrier) ----
    {
        const float* z = zs + e * ROW;
        const float* G = Gs + e * ROW;
        const float* y = ys + e * ROW;
        float r;
        switch (w) {
            case 0:  r = emitW<0>(z, G, y, c1, c2, c3);  break;
            case 1:  r = emitW<1>(z, G, y, c1, c2, c3);  break;
            case 2:  r = emitW<2>(z, G, y, c1, c2, c3);  break;
            case 3:  r = emitW<3>(z, G, y, c1, c2, c3);  break;
            case 4:  r = emitW<4>(z, G, y, c1, c2, c3);  break;
            case 5:  r = emitW<5>(z, G, y, c1, c2, c3);  break;
            case 6:  r = emitW<6>(z, G, y, c1, c2, c3);  break;
            case 7:  r = emitW<7>(z, G, y, c1, c2, c3);  break;
            case 8:  r = emitW<8>(z, G, y, c1, c2, c3);  break;
            case 9:  r = emitW<9>(z, G, y, c1, c2, c3);  break;
            case 10: r = emitW<10>(z, G, y, c1, c2, c3); break;
            case 11: r = emitW<11>(z, G, y, c1, c2, c3); break;
            case 12: r = emitW<12>(z, G, y, c1, c2, c3); break;
            default: r = emitW<13>(z, G, y, c1, c2, c3); break;
        }
        rs[e * ROW + w] = r;                   // [element][qubit], padded
    }
    __syncthreads();

    // ---- Phase 3: coalesced store (448 contiguous floats) ----
    {
        const int e1 = tid / NQ;
        const int u1 = tid - e1 * NQ;
        out[b0 * NQ + tid] = rs[e1 * ROW + u1];
    }
}

extern "C" void kernel_launch(void* const* d_in, const int* in_sizes, int n_in,
                              void* d_out, int out_size) {
    const float* x  = (const float*)d_in[0];
    const float* u3 = (const float*)d_in[1];
    if (n_in >= 2 && in_sizes[0] == NQ * 3 && in_sizes[1] == BATCH * NQ) {
        const float* t = x; x = u3; u3 = t;
    }
    float* out = (float*)d_out;
    qulinear_kernel<<<BATCH / ELEMS, BLK>>>(x, u3, out);
}